// round 12
// baseline (speedup 1.0000x reference)
#include <cuda_runtime.h>
#include <cuda_bf16.h>
#include <cstdint>

// Problem constants (fixed by the dataset)
#define Bsz 8
#define Nn  512
#define Dd  256
#define Ee  16384

// Scratch: AB_bf[b*N + n][0:256] = F@W1_top + b1, [256:512] = F@W1_bot  (4 MB)
__device__ __nv_bfloat16 g_AB[(size_t)Bsz * Nn * 512];

__device__ __forceinline__ uint32_t smem_u32(const void* p) {
    uint32_t a;
    asm("{ .reg .u64 t; cvta.to.shared.u64 t, %1; cvt.u32.u64 %0, t; }"
        : "=r"(a) : "l"(p));
    return a;
}

__device__ __forceinline__ void mma_bf16(
    float c[4], uint32_t a0, uint32_t a1, uint32_t a2, uint32_t a3,
    uint32_t b0, uint32_t b1)
{
    asm volatile(
        "mma.sync.aligned.m16n8k16.row.col.f32.bf16.bf16.f32 "
        "{%0,%1,%2,%3}, {%4,%5,%6,%7}, {%8,%9}, {%0,%1,%2,%3};"
        : "+f"(c[0]), "+f"(c[1]), "+f"(c[2]), "+f"(c[3])
        : "r"(a0), "r"(a1), "r"(a2), "r"(a3), "r"(b0), "r"(b1));
}

// Exact bf16x2 -> float2 unpack via bit ops (bf16 is the top half of f32)
__device__ __forceinline__ float2 bf2_to_f2(uint32_t u) {
    float2 f;
    f.x = __uint_as_float(u << 16);
    f.y = __uint_as_float(u & 0xffff0000u);
    return f;
}

__device__ __forceinline__ uint32_t pack_bf2(float x, float y) {
    __nv_bfloat162 h = __floats2bfloat162_rn(x, y);
    return *(uint32_t*)&h;
}

// ---------------------------------------------------------------------------
// Phase 1 (fused): zero `out`, convert f32 F/W1 -> bf16 smem, then
// tensor GEMM  AB(4096 x 512) = F(4096 x 256) @ Wc(256 x 512).
//   Wc[k][j] = W1[k][j] (j<256) ; W1[256+k][j-256] (j>=256)
// CTA tile M=128 x N=64, whole K resident in smem (no mainloop syncs).
// A smem: bf16 k-pairs, 132 words/row (128 data + 4 pad; banks 4lq+lr distinct).
// B smem: [k][n] bf16 rows, stride 72 (conflict-free ldmatrix.x2.trans).
// Epilogue: +b1 (cols<256), bf16 store to g_AB.
// ---------------------------------------------------------------------------
#define A_WROW 132                     /* uint32 words per A row */
#define B_STR  72                      /* bf16 elems per B row  */
#define SMEM_A_BYTES (128 * A_WROW * 4)            /* 67584 */
#define SMEM_B_BYTES (256 * B_STR * 2)             /* 36864 */
#define SMEM_TOTAL   (SMEM_A_BYTES + SMEM_B_BYTES) /* 104448 */

__global__ __launch_bounds__(256, 2) void gemm_fused_kernel(
    const float* __restrict__ F, const float* __restrict__ W1,
    const float* __restrict__ b1v, __nv_bfloat16* __restrict__ AB,
    float* __restrict__ outz)
{
    extern __shared__ char smem[];
    uint32_t*      As = (uint32_t*)smem;                       // [128][132]
    __nv_bfloat16* Bs = (__nv_bfloat16*)(smem + SMEM_A_BYTES); // [256][72]

    const int tid  = threadIdx.x;
    const int wid  = tid >> 5;
    const int lane = tid & 31;
    const int lq   = lane >> 2;   // 0..7
    const int lr   = lane & 3;    // 0..3

    const int n0 = blockIdx.x * 64;    // 0..448
    const int m0 = blockIdx.y * 128;   // 0..3968

    const int wm = wid >> 1;          // 0..3  (m quadrant, 32 rows)
    const int wn = wid & 1;           // 0..1  (n half, 32 cols)

    // ---- Zero the final output (independent stores, overlap with loads)
    {
        const int gtid = (blockIdx.y * 8 + blockIdx.x) * 256 + tid; // 0..65535
        const float4 z = make_float4(0.f, 0.f, 0.f, 0.f);
#pragma unroll
        for (int i = 0; i < 8; i++)
            *(float4*)(outz + (((size_t)(i * 65536 + gtid)) << 2)) = z;
    }

    const float* Wsrc = (n0 < 256) ? (W1 + n0) : (W1 + 256 * 256 + (n0 - 256));

    // ---- Load + convert A: 128 rows x 256 k f32 -> bf16 pairs in smem.
    // 8192 float4 total; 32 per thread in 4 batches of 8 (MLP=8).
#pragma unroll 1
    for (int bt = 0; bt < 4; bt++) {
        float4 v[8];
#pragma unroll
        for (int u = 0; u < 8; u++) {
            const int idx = (bt * 8 + u) * 256 + tid;      // [0,8192)
            const int m  = idx >> 6;
            const int f4 = idx & 63;
            v[u] = *(const float4*)(F + (size_t)(m0 + m) * 256 + f4 * 4);
        }
#pragma unroll
        for (int u = 0; u < 8; u++) {
            const int idx = (bt * 8 + u) * 256 + tid;
            const int m  = idx >> 6;
            const int f4 = idx & 63;
            uint2 p;
            p.x = pack_bf2(v[u].x, v[u].y);
            p.y = pack_bf2(v[u].z, v[u].w);
            *(uint2*)&As[m * A_WROW + f4 * 2] = p;
        }
    }

    // ---- Load + convert B: 256 k x 64 n f32 -> bf16 rows in smem.
    // 4096 float4 total; 16 per thread in 2 batches of 8.
#pragma unroll 1
    for (int bt = 0; bt < 2; bt++) {
        float4 v[8];
#pragma unroll
        for (int u = 0; u < 8; u++) {
            const int idx = (bt * 8 + u) * 256 + tid;      // [0,4096)
            const int k  = idx >> 4;
            const int f4 = idx & 15;
            v[u] = *(const float4*)(Wsrc + (size_t)k * 256 + f4 * 4);
        }
#pragma unroll
        for (int u = 0; u < 8; u++) {
            const int idx = (bt * 8 + u) * 256 + tid;
            const int k  = idx >> 4;
            const int f4 = idx & 15;
            uint2 p;
            p.x = pack_bf2(v[u].x, v[u].y);
            p.y = pack_bf2(v[u].z, v[u].w);
            *(uint2*)&Bs[k * B_STR + f4 * 4] = p;
        }
    }

    __syncthreads();   // the only sync: smem now holds all of A and B

    const uint32_t bs_b = smem_u32(Bs);

    float c[2][4][4] = {};            // [m-tile][n-tile][frag]

#pragma unroll 1
    for (int chunk = 0; chunk < 8; chunk++) {
#pragma unroll
        for (int ks = 0; ks < 2; ks++) {
            const int kp0 = chunk * 16 + ks * 8;    // k-pair base
            uint32_t a[2][4];
#pragma unroll
            for (int ii = 0; ii < 2; ii++) {
                const int rb = (wm * 32 + ii * 16 + lq) * A_WROW + kp0 + lr;
                a[ii][0] = As[rb];
                a[ii][1] = As[rb + 8 * A_WROW];
                a[ii][2] = As[rb + 4];
                a[ii][3] = As[rb + 8 * A_WROW + 4];
            }
            uint32_t b[4][2];
            const int krow = chunk * 32 + ks * 16 + (lane & 15);
#pragma unroll
            for (int j = 0; j < 4; j++) {
                const int ncol = wn * 32 + j * 8;
                const uint32_t addr = bs_b + (uint32_t)((krow * B_STR + ncol) * 2);
                asm volatile(
                    "ldmatrix.sync.aligned.m8n8.x2.trans.shared.b16 {%0,%1}, [%2];"
                    : "=r"(b[j][0]), "=r"(b[j][1]) : "r"(addr));
            }
#pragma unroll
            for (int ii = 0; ii < 2; ii++)
#pragma unroll
                for (int j = 0; j < 4; j++)
                    mma_bf16(c[ii][j], a[ii][0], a[ii][1], a[ii][2], a[ii][3],
                             b[j][0], b[j][1]);
        }
    }

    // ---- Epilogue: add b1 (cols<256 only), pack to bf16, store.
    float2 bias[4];
#pragma unroll
    for (int j = 0; j < 4; j++) {
        const int col = n0 + wn * 32 + j * 8 + 2 * lr;
        bias[j] = (n0 < 256) ? *(const float2*)(b1v + col)
                             : make_float2(0.f, 0.f);
    }
#pragma unroll
    for (int i = 0; i < 2; i++) {
        const int rbase = m0 + wm * 32 + i * 16 + lq;
#pragma unroll
        for (int j = 0; j < 4; j++) {
            const int col = n0 + wn * 32 + j * 8 + 2 * lr;
            float2 v0 = make_float2(c[i][j][0] + bias[j].x, c[i][j][1] + bias[j].y);
            float2 v1 = make_float2(c[i][j][2] + bias[j].x, c[i][j][3] + bias[j].y);
            *(__nv_bfloat162*)(AB + (size_t)rbase * 512 + col) =
                __float22bfloat162_rn(v0);
            *(__nv_bfloat162*)(AB + (size_t)(rbase + 8) * 512 + col) =
                __float22bfloat162_rn(v1);
        }
    }
}

// ---------------------------------------------------------------------------
// Phase 2: edge MLP tail + scatter (unchanged from R11; measured stable).
// One warp per 4 edges. bf16x2 add/relu, exact shift unpack, fp32 dot,
// 6-shfl multi-edge reduce, parallel sigmoid.
// ---------------------------------------------------------------------------
__global__ __launch_bounds__(256) void edge_kernel(
    const __nv_bfloat16* __restrict__ AB,
    const float* __restrict__ W2,
    const float* __restrict__ b2,
    const void* __restrict__ edge_raw,
    float* __restrict__ out)
{
    const int tid  = threadIdx.x;
    const int warp = tid >> 5;
    const int lane = tid & 31;
    const int ch   = lane * 8;          // 8 channels per lane

    const int*       e32 = (const int*)edge_raw;
    const long long* e64 = (const long long*)edge_raw;

    // In-warp dtype detection: int64 buffer has all odd words zero.
    int vdet = e32[2 * lane + 1];
    unsigned any = __ballot_sync(0xffffffffu, vdet != 0);
    const bool is64 = (any == 0u);

    float w[8];
    *(float4*)&w[0] = *(const float4*)(W2 + ch);
    *(float4*)&w[4] = *(const float4*)(W2 + ch + 4);
    const float b2v = b2[0];

    const int wslot = blockIdx.x * 8 + warp;  // 0..32767

    uint32_t key[4], aoff[4], boff[4];
#pragma unroll
    for (int r = 0; r < 4; r++) {
        const int g = wslot * 4 + r;            // 0..131071  (b,e) pair
        const int b = g >> 14;                  // E = 16384
        const int e = g & (Ee - 1);
        int src, dst;
        if (is64) {
            src = (int)e64[e];
            dst = (int)e64[Ee + e];
        } else {
            src = e32[e];
            dst = e32[Ee + e];
        }
        key[r]  = ((uint32_t)b << 18) | ((uint32_t)src << 9) | (uint32_t)dst;
        aoff[r] = (((uint32_t)(b * Nn + src)) << 9) + ch;
        boff[r] = (((uint32_t)(b * Nn + dst)) << 9) + 256 + ch;
    }

    // Issue all 8 row-gathers up front (MLP=8)
    uint4 av[4], bv[4];
#pragma unroll
    for (int r = 0; r < 4; r++) {
        av[r] = *(const uint4*)(AB + aoff[r]);
        bv[r] = *(const uint4*)(AB + boff[r]);
    }

    const __nv_bfloat162 z2 = __float2bfloat162_rn(0.f);
    float acc[4];
#pragma unroll
    for (int r = 0; r < 4; r++) {
        const __nv_bfloat162* ap = (const __nv_bfloat162*)&av[r];
        const __nv_bfloat162* bp = (const __nv_bfloat162*)&bv[r];
        float a = 0.f;
#pragma unroll
        for (int p = 0; p < 4; p++) {
            __nv_bfloat162 h = __hmax2(__hadd2(ap[p], bp[p]), z2);
            float2 f = bf2_to_f2(*(const uint32_t*)&h);
            a = fmaf(f.x, w[2 * p], a);
            a = fmaf(f.y, w[2 * p + 1], a);
        }
        acc[r] = a;
    }

    // ---- Multi-edge reduction: 6 shfls reduce all 4 edges.
    const bool hi16 = (lane & 16) != 0;
    float send, recv, sA, sB, t;

    send = hi16 ? acc[0] : acc[2];
    recv = __shfl_xor_sync(0xffffffffu, send, 16);
    sA   = (hi16 ? acc[2] : acc[0]) + recv;   // lanes<16: e0, lanes>=16: e2

    send = hi16 ? acc[1] : acc[3];
    recv = __shfl_xor_sync(0xffffffffu, send, 16);
    sB   = (hi16 ? acc[3] : acc[1]) + recv;   // lanes<16: e1, lanes>=16: e3

    const bool hi8 = (lane & 8) != 0;
    send = hi8 ? sA : sB;
    recv = __shfl_xor_sync(0xffffffffu, send, 8);
    t    = (hi8 ? sB : sA) + recv;            // group g holds edge g

    t += __shfl_xor_sync(0xffffffffu, t, 4);
    t += __shfl_xor_sync(0xffffffffu, t, 2);
    t += __shfl_xor_sync(0xffffffffu, t, 1);

    const int g = lane >> 3;
    const uint32_t k = (g & 2) ? ((g & 1) ? key[3] : key[2])
                               : ((g & 1) ? key[1] : key[0]);
    const float s = 1.0f / (1.0f + __expf(-(t + b2v)));
    if ((lane & 7) == 0)
        out[k] = s;
}

// ---------------------------------------------------------------------------
extern "C" void kernel_launch(void* const* d_in, const int* in_sizes, int n_in,
                              void* d_out, int out_size)
{
    const float* features = (const float*)d_in[0];   // (8,512,256)
    const float* W1       = (const float*)d_in[1];   // (512,256)
    const float* b1       = (const float*)d_in[2];   // (256)
    const float* W2       = (const float*)d_in[3];   // (256,1)
    const float* b2       = (const float*)d_in[4];   // (1)
    const void*  edge     = d_in[5];                 // (2,16384) int32 or int64
    float*       out      = (float*)d_out;           // (8,512,512)

    __nv_bfloat16* AB;
    cudaGetSymbolAddress((void**)&AB, g_AB);

    cudaFuncSetAttribute(gemm_fused_kernel,
                         cudaFuncAttributeMaxDynamicSharedMemorySize, SMEM_TOTAL);

    // Phase 1 (fused): zero out + convert + GEMM + fold b1
    dim3 ggrid(8, 32);   // N-tiles x M-tiles
    gemm_fused_kernel<<<ggrid, 256, SMEM_TOTAL>>>(features, W1, b1, AB, out);

    // Phase 2: edge MLP tail + scatter (4 edges per warp)
    edge_kernel<<<4096, 256>>>(AB, W2, b2, edge, out);
}

// round 13
// speedup vs baseline: 1.1887x; 1.1887x over previous
#include <cuda_runtime.h>
#include <cuda_bf16.h>
#include <cstdint>

// Problem constants (fixed by the dataset)
#define Bsz 8
#define Nn  512
#define Dd  256
#define Ee  16384

// Scratch: AB_bf[b*N + n][0:256] = F@W1_top + b1, [256:512] = F@W1_bot  (4 MB)
__device__ __nv_bfloat16 g_AB[(size_t)Bsz * Nn * 512];

__device__ __forceinline__ uint32_t smem_u32(const void* p) {
    uint32_t a;
    asm("{ .reg .u64 t; cvta.to.shared.u64 t, %1; cvt.u32.u64 %0, t; }"
        : "=r"(a) : "l"(p));
    return a;
}

__device__ __forceinline__ void cp16(uint32_t dst, const void* src) {
    asm volatile("cp.async.cg.shared.global [%0], [%1], 16;"
                 :: "r"(dst), "l"(src));
}

__device__ __forceinline__ void mma_bf16(
    float c[4], uint32_t a0, uint32_t a1, uint32_t a2, uint32_t a3,
    uint32_t b0, uint32_t b1)
{
    asm volatile(
        "mma.sync.aligned.m16n8k16.row.col.f32.bf16.bf16.f32 "
        "{%0,%1,%2,%3}, {%4,%5,%6,%7}, {%8,%9}, {%0,%1,%2,%3};"
        : "+f"(c[0]), "+f"(c[1]), "+f"(c[2]), "+f"(c[3])
        : "r"(a0), "r"(a1), "r"(a2), "r"(a3), "r"(b0), "r"(b1));
}

// Exact bf16x2 -> float2 unpack via bit ops (bf16 is the top half of f32)
__device__ __forceinline__ float2 bf2_to_f2(uint32_t u) {
    float2 f;
    f.x = __uint_as_float(u << 16);
    f.y = __uint_as_float(u & 0xffff0000u);
    return f;
}

__device__ __forceinline__ uint32_t pack_bf2(float x, float y) {
    __nv_bfloat162 h = __floats2bfloat162_rn(x, y);
    return *(uint32_t*)&h;
}

// ---------------------------------------------------------------------------
// Phase 1 (fused): zero `out`; convert B (W1 concat) f32->bf16 smem once;
// stream A (F) f32 via cp.async double-buffer, converting at fragment load.
//   AB(4096 x 512) = F(4096 x 256) @ Wc(256 x 512), fp32 accum.
//   Wc[k][j] = W1[k][j] (j<256) ; W1[256+k][j-256] (j>=256)
// CTA tile M=128 x N=64, K chunked by 32.
// A smem: f32, 40 words/row (32 data + 8 pad): LDS.64 banks 8lq+2lr distinct.
// B smem: [k][n] bf16 rows, stride 72 (conflict-free ldmatrix.x2.trans).
// Epilogue: +b1 (cols<256), bf16 store to g_AB.
// ---------------------------------------------------------------------------
#define AF_STR 40                                  /* f32 words per A row */
#define AF_CHUNK_BYTES (128 * AF_STR * 4)          /* 20480 per buffer */
#define B_STR  72                                  /* bf16 elems per B row */
#define SMEM_B_OFF   (2 * AF_CHUNK_BYTES)          /* 40960 */
#define SMEM_TOTAL   (SMEM_B_OFF + 256 * B_STR * 2) /* 77824 */

__global__ __launch_bounds__(256) void gemm_fused_kernel(
    const float* __restrict__ F, const float* __restrict__ W1,
    const float* __restrict__ b1v, __nv_bfloat16* __restrict__ AB,
    float* __restrict__ outz)
{
    extern __shared__ char smem[];
    float*         Af = (float*)smem;                        // [2][128][40]
    __nv_bfloat16* Bs = (__nv_bfloat16*)(smem + SMEM_B_OFF); // [256][72]

    const int tid  = threadIdx.x;
    const int wid  = tid >> 5;
    const int lane = tid & 31;
    const int lq   = lane >> 2;   // 0..7
    const int lr   = lane & 3;    // 0..3

    const int n0 = blockIdx.x * 64;    // 0..448
    const int m0 = blockIdx.y * 128;   // 0..3968

    const int wm = wid >> 1;          // 0..3  (m quadrant, 32 rows)
    const int wn = wid & 1;           // 0..1  (n half, 32 cols)

    const uint32_t af_base[2] = { smem_u32(Af),
                                  smem_u32(Af) + AF_CHUNK_BYTES };

    // cp.async assignment: A chunk = 128 rows x 32 f32 = 1024 x 16B segs,
    // 4 per thread: idx = u*256+tid, row = idx>>3, seg = idx&7.
    #define ISSUE_CHUNK(buf, kc_) do {                                        \
        _Pragma("unroll")                                                     \
        for (int u = 0; u < 4; u++) {                                         \
            const int idx = u * 256 + tid;                                    \
            const int row = idx >> 3;                                         \
            const int seg = idx & 7;                                          \
            cp16(af_base[buf] + (uint32_t)(row * (AF_STR * 4) + seg * 16),    \
                 F + (size_t)(m0 + row) * 256 + (kc_) + seg * 4);             \
        }                                                                     \
        asm volatile("cp.async.commit_group;" ::: "memory");                  \
    } while (0)

    ISSUE_CHUNK(0, 0);

    // ---- Zero the final output (overlaps with chunk-0 cp.async)
    {
        const int gtid = (blockIdx.y * 8 + blockIdx.x) * 256 + tid; // 0..65535
        const float4 z = make_float4(0.f, 0.f, 0.f, 0.f);
#pragma unroll
        for (int i = 0; i < 8; i++)
            *(float4*)(outz + (((size_t)(i * 65536 + gtid)) << 2)) = z;
    }

    // ---- Convert B slice once: 256 k x 64 n f32 -> bf16 rows in smem.
    {
        const float* Wsrc = (n0 < 256) ? (W1 + n0)
                                       : (W1 + 256 * 256 + (n0 - 256));
#pragma unroll 1
        for (int bt = 0; bt < 2; bt++) {
            float4 v[8];
#pragma unroll
            for (int u = 0; u < 8; u++) {
                const int idx = (bt * 8 + u) * 256 + tid;   // [0,4096)
                const int k  = idx >> 4;
                const int f4 = idx & 15;
                v[u] = *(const float4*)(Wsrc + (size_t)k * 256 + f4 * 4);
            }
#pragma unroll
            for (int u = 0; u < 8; u++) {
                const int idx = (bt * 8 + u) * 256 + tid;
                const int k  = idx >> 4;
                const int f4 = idx & 15;
                uint2 p;
                p.x = pack_bf2(v[u].x, v[u].y);
                p.y = pack_bf2(v[u].z, v[u].w);
                *(uint2*)&Bs[k * B_STR + f4 * 4] = p;
            }
        }
    }

    const uint32_t bs_b = smem_u32(Bs);

    float c[2][4][4] = {};            // [m-tile][n-tile][frag]

#pragma unroll 1
    for (int i = 0; i < 8; i++) {
        const int buf = i & 1;
        if (i < 7) {
            ISSUE_CHUNK(buf ^ 1, (i + 1) * 32);
            asm volatile("cp.async.wait_group 1;" ::: "memory");
        } else {
            asm volatile("cp.async.wait_group 0;" ::: "memory");
        }
        __syncthreads();

        const float* Ab = Af + buf * (AF_CHUNK_BYTES / 4);

#pragma unroll
        for (int ks = 0; ks < 2; ks++) {
            const int k0 = ks * 16;    // k base within chunk (f32 index)
            uint32_t a[2][4];
#pragma unroll
            for (int ii = 0; ii < 2; ii++) {
                const int rb = (wm * 32 + ii * 16 + lq) * AF_STR + k0 + 2 * lr;
                float2 p0 = *(const float2*)&Ab[rb];
                float2 p1 = *(const float2*)&Ab[rb + 8 * AF_STR];
                float2 p2 = *(const float2*)&Ab[rb + 8];
                float2 p3 = *(const float2*)&Ab[rb + 8 * AF_STR + 8];
                a[ii][0] = pack_bf2(p0.x, p0.y);
                a[ii][1] = pack_bf2(p1.x, p1.y);
                a[ii][2] = pack_bf2(p2.x, p2.y);
                a[ii][3] = pack_bf2(p3.x, p3.y);
            }
            uint32_t b[4][2];
            const int krow = i * 32 + ks * 16 + (lane & 15);
#pragma unroll
            for (int j = 0; j < 4; j++) {
                const int ncol = wn * 32 + j * 8;
                const uint32_t addr = bs_b + (uint32_t)((krow * B_STR + ncol) * 2);
                asm volatile(
                    "ldmatrix.sync.aligned.m8n8.x2.trans.shared.b16 {%0,%1}, [%2];"
                    : "=r"(b[j][0]), "=r"(b[j][1]) : "r"(addr));
            }
#pragma unroll
            for (int ii = 0; ii < 2; ii++)
#pragma unroll
                for (int j = 0; j < 4; j++)
                    mma_bf16(c[ii][j], a[ii][0], a[ii][1], a[ii][2], a[ii][3],
                             b[j][0], b[j][1]);
        }
        __syncthreads();
    }

    // ---- Epilogue: add b1 (cols<256 only), pack to bf16, store.
    float2 bias[4];
#pragma unroll
    for (int j = 0; j < 4; j++) {
        const int col = n0 + wn * 32 + j * 8 + 2 * lr;
        bias[j] = (n0 < 256) ? *(const float2*)(b1v + col)
                             : make_float2(0.f, 0.f);
    }
#pragma unroll
    for (int i = 0; i < 2; i++) {
        const int rbase = m0 + wm * 32 + i * 16 + lq;
#pragma unroll
        for (int j = 0; j < 4; j++) {
            const int col = n0 + wn * 32 + j * 8 + 2 * lr;
            float2 v0 = make_float2(c[i][j][0] + bias[j].x, c[i][j][1] + bias[j].y);
            float2 v1 = make_float2(c[i][j][2] + bias[j].x, c[i][j][3] + bias[j].y);
            *(__nv_bfloat162*)(AB + (size_t)rbase * 512 + col) =
                __float22bfloat162_rn(v0);
            *(__nv_bfloat162*)(AB + (size_t)(rbase + 8) * 512 + col) =
                __float22bfloat162_rn(v1);
        }
    }
}

// ---------------------------------------------------------------------------
// Phase 2: edge MLP tail + scatter (unchanged; measured stable ~15.3us).
// One warp per 4 edges. bf16x2 add/relu, exact shift unpack, fp32 dot,
// 6-shfl multi-edge reduce, parallel sigmoid.
// ---------------------------------------------------------------------------
__global__ __launch_bounds__(256) void edge_kernel(
    const __nv_bfloat16* __restrict__ AB,
    const float* __restrict__ W2,
    const float* __restrict__ b2,
    const void* __restrict__ edge_raw,
    float* __restrict__ out)
{
    const int tid  = threadIdx.x;
    const int warp = tid >> 5;
    const int lane = tid & 31;
    const int ch   = lane * 8;          // 8 channels per lane

    const int*       e32 = (const int*)edge_raw;
    const long long* e64 = (const long long*)edge_raw;

    // In-warp dtype detection: int64 buffer has all odd words zero.
    int vdet = e32[2 * lane + 1];
    unsigned any = __ballot_sync(0xffffffffu, vdet != 0);
    const bool is64 = (any == 0u);

    float w[8];
    *(float4*)&w[0] = *(const float4*)(W2 + ch);
    *(float4*)&w[4] = *(const float4*)(W2 + ch + 4);
    const float b2v = b2[0];

    const int wslot = blockIdx.x * 8 + warp;  // 0..32767

    uint32_t key[4], aoff[4], boff[4];
#pragma unroll
    for (int r = 0; r < 4; r++) {
        const int g = wslot * 4 + r;            // 0..131071  (b,e) pair
        const int b = g >> 14;                  // E = 16384
        const int e = g & (Ee - 1);
        int src, dst;
        if (is64) {
            src = (int)e64[e];
            dst = (int)e64[Ee + e];
        } else {
            src = e32[e];
            dst = e32[Ee + e];
        }
        key[r]  = ((uint32_t)b << 18) | ((uint32_t)src << 9) | (uint32_t)dst;
        aoff[r] = (((uint32_t)(b * Nn + src)) << 9) + ch;
        boff[r] = (((uint32_t)(b * Nn + dst)) << 9) + 256 + ch;
    }

    // Issue all 8 row-gathers up front (MLP=8)
    uint4 av[4], bv[4];
#pragma unroll
    for (int r = 0; r < 4; r++) {
        av[r] = *(const uint4*)(AB + aoff[r]);
        bv[r] = *(const uint4*)(AB + boff[r]);
    }

    const __nv_bfloat162 z2 = __float2bfloat162_rn(0.f);
    float acc[4];
#pragma unroll
    for (int r = 0; r < 4; r++) {
        const __nv_bfloat162* ap = (const __nv_bfloat162*)&av[r];
        const __nv_bfloat162* bp = (const __nv_bfloat162*)&bv[r];
        float a = 0.f;
#pragma unroll
        for (int p = 0; p < 4; p++) {
            __nv_bfloat162 h = __hmax2(__hadd2(ap[p], bp[p]), z2);
            float2 f = bf2_to_f2(*(const uint32_t*)&h);
            a = fmaf(f.x, w[2 * p], a);
            a = fmaf(f.y, w[2 * p + 1], a);
        }
        acc[r] = a;
    }

    // ---- Multi-edge reduction: 6 shfls reduce all 4 edges.
    const bool hi16 = (lane & 16) != 0;
    float send, recv, sA, sB, t;

    send = hi16 ? acc[0] : acc[2];
    recv = __shfl_xor_sync(0xffffffffu, send, 16);
    sA   = (hi16 ? acc[2] : acc[0]) + recv;   // lanes<16: e0, lanes>=16: e2

    send = hi16 ? acc[1] : acc[3];
    recv = __shfl_xor_sync(0xffffffffu, send, 16);
    sB   = (hi16 ? acc[3] : acc[1]) + recv;   // lanes<16: e1, lanes>=16: e3

    const bool hi8 = (lane & 8) != 0;
    send = hi8 ? sA : sB;
    recv = __shfl_xor_sync(0xffffffffu, send, 8);
    t    = (hi8 ? sB : sA) + recv;            // group g holds edge g

    t += __shfl_xor_sync(0xffffffffu, t, 4);
    t += __shfl_xor_sync(0xffffffffu, t, 2);
    t += __shfl_xor_sync(0xffffffffu, t, 1);

    const int g = lane >> 3;
    const uint32_t k = (g & 2) ? ((g & 1) ? key[3] : key[2])
                               : ((g & 1) ? key[1] : key[0]);
    const float s = 1.0f / (1.0f + __expf(-(t + b2v)));
    if ((lane & 7) == 0)
        out[k] = s;
}

// ---------------------------------------------------------------------------
extern "C" void kernel_launch(void* const* d_in, const int* in_sizes, int n_in,
                              void* d_out, int out_size)
{
    const float* features = (const float*)d_in[0];   // (8,512,256)
    const float* W1       = (const float*)d_in[1];   // (512,256)
    const float* b1       = (const float*)d_in[2];   // (256)
    const float* W2       = (const float*)d_in[3];   // (256,1)
    const float* b2       = (const float*)d_in[4];   // (1)
    const void*  edge     = d_in[5];                 // (2,16384) int32 or int64
    float*       out      = (float*)d_out;           // (8,512,512)

    __nv_bfloat16* AB;
    cudaGetSymbolAddress((void**)&AB, g_AB);

    cudaFuncSetAttribute(gemm_fused_kernel,
                         cudaFuncAttributeMaxDynamicSharedMemorySize, SMEM_TOTAL);

    // Phase 1 (fused): zero out + B convert + cp.async f32 A stream + GEMM
    dim3 ggrid(8, 32);   // N-tiles x M-tiles
    gemm_fused_kernel<<<ggrid, 256, SMEM_TOTAL>>>(features, W1, b1, AB, out);

    // Phase 2: edge MLP tail + scatter (4 edges per warp)
    edge_kernel<<<4096, 256>>>(AB, W2, b2, edge, out);
}

// round 14
// speedup vs baseline: 1.2874x; 1.0830x over previous
#include <cuda_runtime.h>
#include <cuda_bf16.h>
#include <cstdint>

// Problem constants (fixed by the dataset)
#define Bsz 8
#define Nn  512
#define Dd  256
#define Ee  16384

// Scratch: AB_bf[b*N + n][0:256] = F@W1_top + b1, [256:512] = F@W1_bot  (4 MB)
__device__ __nv_bfloat16 g_AB[(size_t)Bsz * Nn * 512];

__device__ __forceinline__ uint32_t smem_u32(const void* p) {
    uint32_t a;
    asm("{ .reg .u64 t; cvta.to.shared.u64 t, %1; cvt.u32.u64 %0, t; }"
        : "=r"(a) : "l"(p));
    return a;
}

__device__ __forceinline__ void cp16(uint32_t dst, const void* src) {
    asm volatile("cp.async.cg.shared.global [%0], [%1], 16;"
                 :: "r"(dst), "l"(src));
}

__device__ __forceinline__ void mma_bf16(
    float c[4], uint32_t a0, uint32_t a1, uint32_t a2, uint32_t a3,
    uint32_t b0, uint32_t b1)
{
    asm volatile(
        "mma.sync.aligned.m16n8k16.row.col.f32.bf16.bf16.f32 "
        "{%0,%1,%2,%3}, {%4,%5,%6,%7}, {%8,%9}, {%0,%1,%2,%3};"
        : "+f"(c[0]), "+f"(c[1]), "+f"(c[2]), "+f"(c[3])
        : "r"(a0), "r"(a1), "r"(a2), "r"(a3), "r"(b0), "r"(b1));
}

// Exact bf16x2 -> float2 unpack via bit ops (bf16 is the top half of f32)
__device__ __forceinline__ float2 bf2_to_f2(uint32_t u) {
    float2 f;
    f.x = __uint_as_float(u << 16);
    f.y = __uint_as_float(u & 0xffff0000u);
    return f;
}

__device__ __forceinline__ uint32_t pack_bf2(float x, float y) {
    __nv_bfloat162 h = __floats2bfloat162_rn(x, y);
    return *(uint32_t*)&h;
}

// ---------------------------------------------------------------------------
// Phase 1 (fused): zero `out`; convert B (W1 concat) f32->bf16 smem once;
// stream A (F) f32 via cp.async double-buffer, converting at fragment load.
//   AB(4096 x 512) = F(4096 x 256) @ Wc(256 x 512), fp32 accum.
//   Wc[k][j] = W1[k][j] (j<256) ; W1[256+k][j-256] (j>=256)
// CTA tile M=128 x N=64, K chunked by 32.
// A smem: f32, 40 words/row (32 data + 8 pad): LDS.64 banks 8lq+2lr distinct.
// B smem: [k][n] bf16 rows, stride 72 (conflict-free ldmatrix.x2.trans).
// Epilogue: +b1 (cols<256), bf16 store to g_AB.
// ---------------------------------------------------------------------------
#define AF_STR 40                                  /* f32 words per A row */
#define AF_CHUNK_BYTES (128 * AF_STR * 4)          /* 20480 per buffer */
#define B_STR  72                                  /* bf16 elems per B row */
#define SMEM_B_OFF   (2 * AF_CHUNK_BYTES)          /* 40960 */
#define SMEM_TOTAL   (SMEM_B_OFF + 256 * B_STR * 2) /* 77824 */

__global__ __launch_bounds__(256) void gemm_fused_kernel(
    const float* __restrict__ F, const float* __restrict__ W1,
    const float* __restrict__ b1v, __nv_bfloat16* __restrict__ AB,
    float* __restrict__ outz)
{
    extern __shared__ char smem[];
    float*         Af = (float*)smem;                        // [2][128][40]
    __nv_bfloat16* Bs = (__nv_bfloat16*)(smem + SMEM_B_OFF); // [256][72]

    const int tid  = threadIdx.x;
    const int wid  = tid >> 5;
    const int lane = tid & 31;
    const int lq   = lane >> 2;   // 0..7
    const int lr   = lane & 3;    // 0..3

    const int n0 = blockIdx.x * 64;    // 0..448
    const int m0 = blockIdx.y * 128;   // 0..3968

    const int wm = wid >> 1;          // 0..3  (m quadrant, 32 rows)
    const int wn = wid & 1;           // 0..1  (n half, 32 cols)

    const uint32_t af_base[2] = { smem_u32(Af),
                                  smem_u32(Af) + AF_CHUNK_BYTES };

    // cp.async assignment: A chunk = 128 rows x 32 f32 = 1024 x 16B segs,
    // 4 per thread: idx = u*256+tid, row = idx>>3, seg = idx&7.
    #define ISSUE_CHUNK(buf, kc_) do {                                        \
        _Pragma("unroll")                                                     \
        for (int u = 0; u < 4; u++) {                                         \
            const int idx = u * 256 + tid;                                    \
            const int row = idx >> 3;                                         \
            const int seg = idx & 7;                                          \
            cp16(af_base[buf] + (uint32_t)(row * (AF_STR * 4) + seg * 16),    \
                 F + (size_t)(m0 + row) * 256 + (kc_) + seg * 4);             \
        }                                                                     \
        asm volatile("cp.async.commit_group;" ::: "memory");                  \
    } while (0)

    ISSUE_CHUNK(0, 0);

    // ---- Zero the final output (overlaps with chunk-0 cp.async)
    {
        const int gtid = (blockIdx.y * 8 + blockIdx.x) * 256 + tid; // 0..65535
        const float4 z = make_float4(0.f, 0.f, 0.f, 0.f);
#pragma unroll
        for (int i = 0; i < 8; i++)
            *(float4*)(outz + (((size_t)(i * 65536 + gtid)) << 2)) = z;
    }

    // ---- Convert B slice once: 256 k x 64 n f32 -> bf16 rows in smem.
    {
        const float* Wsrc = (n0 < 256) ? (W1 + n0)
                                       : (W1 + 256 * 256 + (n0 - 256));
#pragma unroll 1
        for (int bt = 0; bt < 2; bt++) {
            float4 v[8];
#pragma unroll
            for (int u = 0; u < 8; u++) {
                const int idx = (bt * 8 + u) * 256 + tid;   // [0,4096)
                const int k  = idx >> 4;
                const int f4 = idx & 15;
                v[u] = *(const float4*)(Wsrc + (size_t)k * 256 + f4 * 4);
            }
#pragma unroll
            for (int u = 0; u < 8; u++) {
                const int idx = (bt * 8 + u) * 256 + tid;
                const int k  = idx >> 4;
                const int f4 = idx & 15;
                uint2 p;
                p.x = pack_bf2(v[u].x, v[u].y);
                p.y = pack_bf2(v[u].z, v[u].w);
                *(uint2*)&Bs[k * B_STR + f4 * 4] = p;
            }
        }
    }

    const uint32_t bs_b = smem_u32(Bs);

    float c[2][4][4] = {};            // [m-tile][n-tile][frag]

#pragma unroll 1
    for (int i = 0; i < 8; i++) {
        const int buf = i & 1;
        if (i < 7) {
            ISSUE_CHUNK(buf ^ 1, (i + 1) * 32);
            asm volatile("cp.async.wait_group 1;" ::: "memory");
        } else {
            asm volatile("cp.async.wait_group 0;" ::: "memory");
        }
        __syncthreads();

        const float* Ab = Af + buf * (AF_CHUNK_BYTES / 4);

#pragma unroll
        for (int ks = 0; ks < 2; ks++) {
            const int k0 = ks * 16;    // k base within chunk (f32 index)
            uint32_t a[2][4];
#pragma unroll
            for (int ii = 0; ii < 2; ii++) {
                const int rb = (wm * 32 + ii * 16 + lq) * AF_STR + k0 + 2 * lr;
                float2 p0 = *(const float2*)&Ab[rb];
                float2 p1 = *(const float2*)&Ab[rb + 8 * AF_STR];
                float2 p2 = *(const float2*)&Ab[rb + 8];
                float2 p3 = *(const float2*)&Ab[rb + 8 * AF_STR + 8];
                a[ii][0] = pack_bf2(p0.x, p0.y);
                a[ii][1] = pack_bf2(p1.x, p1.y);
                a[ii][2] = pack_bf2(p2.x, p2.y);
                a[ii][3] = pack_bf2(p3.x, p3.y);
            }
            uint32_t b[4][2];
            const int krow = i * 32 + ks * 16 + (lane & 15);
#pragma unroll
            for (int j = 0; j < 4; j++) {
                const int ncol = wn * 32 + j * 8;
                const uint32_t addr = bs_b + (uint32_t)((krow * B_STR + ncol) * 2);
                asm volatile(
                    "ldmatrix.sync.aligned.m8n8.x2.trans.shared.b16 {%0,%1}, [%2];"
                    : "=r"(b[j][0]), "=r"(b[j][1]) : "r"(addr));
            }
#pragma unroll
            for (int ii = 0; ii < 2; ii++)
#pragma unroll
                for (int j = 0; j < 4; j++)
                    mma_bf16(c[ii][j], a[ii][0], a[ii][1], a[ii][2], a[ii][3],
                             b[j][0], b[j][1]);
        }
        __syncthreads();
    }

    // ---- Epilogue: add b1 (cols<256 only), pack to bf16, store.
    float2 bias[4];
#pragma unroll
    for (int j = 0; j < 4; j++) {
        const int col = n0 + wn * 32 + j * 8 + 2 * lr;
        bias[j] = (n0 < 256) ? *(const float2*)(b1v + col)
                             : make_float2(0.f, 0.f);
    }
#pragma unroll
    for (int i = 0; i < 2; i++) {
        const int rbase = m0 + wm * 32 + i * 16 + lq;
#pragma unroll
        for (int j = 0; j < 4; j++) {
            const int col = n0 + wn * 32 + j * 8 + 2 * lr;
            float2 v0 = make_float2(c[i][j][0] + bias[j].x, c[i][j][1] + bias[j].y);
            float2 v1 = make_float2(c[i][j][2] + bias[j].x, c[i][j][3] + bias[j].y);
            *(__nv_bfloat162*)(AB + (size_t)rbase * 512 + col) =
                __float22bfloat162_rn(v0);
            *(__nv_bfloat162*)(AB + (size_t)(rbase + 8) * 512 + col) =
                __float22bfloat162_rn(v1);
        }
    }
}

// ---------------------------------------------------------------------------
// Phase 2: edge MLP tail + scatter.
// One warp per 4 CONSECUTIVE edges: index loads vectorized (int4/longlong2,
// 16B-aligned since e0 % 4 == 0 and groups never cross the E boundary),
// batch b warp-uniform -> base = b<<18 hoisted; key shares srow computation.
// bf16x2 add/relu, exact shift unpack, fp32 dot, 6-shfl multi-edge reduce.
// ---------------------------------------------------------------------------
__global__ __launch_bounds__(256) void edge_kernel(
    const __nv_bfloat16* __restrict__ AB,
    const float* __restrict__ W2,
    const float* __restrict__ b2,
    const void* __restrict__ edge_raw,
    float* __restrict__ out)
{
    const int tid  = threadIdx.x;
    const int warp = tid >> 5;
    const int lane = tid & 31;
    const int ch   = lane * 8;          // 8 channels per lane

    const int*       e32 = (const int*)edge_raw;
    const long long* e64 = (const long long*)edge_raw;

    // In-warp dtype detection: int64 buffer has all odd words zero.
    int vdet = e32[2 * lane + 1];
    unsigned any = __ballot_sync(0xffffffffu, vdet != 0);
    const bool is64 = (any == 0u);

    float w[8];
    *(float4*)&w[0] = *(const float4*)(W2 + ch);
    *(float4*)&w[4] = *(const float4*)(W2 + ch + 4);
    const float b2v = b2[0];

    const int wslot = blockIdx.x * 8 + warp;   // 0..32767
    const int g0    = wslot * 4;               // first (b,e) pair
    const int e0    = g0 & (Ee - 1);           // e0 % 4 == 0
    const uint32_t base = ((uint32_t)(g0 >> 14)) << 18;   // b * N * 512

    // ---- Vectorized index loads (all lanes same address: broadcast)
    int src[4], dst[4];
    if (is64) {
        longlong2 s01 = *(const longlong2*)(e64 + e0);
        longlong2 s23 = *(const longlong2*)(e64 + e0 + 2);
        longlong2 d01 = *(const longlong2*)(e64 + Ee + e0);
        longlong2 d23 = *(const longlong2*)(e64 + Ee + e0 + 2);
        src[0] = (int)s01.x; src[1] = (int)s01.y;
        src[2] = (int)s23.x; src[3] = (int)s23.y;
        dst[0] = (int)d01.x; dst[1] = (int)d01.y;
        dst[2] = (int)d23.x; dst[3] = (int)d23.y;
    } else {
        int4 s = *(const int4*)(e32 + e0);
        int4 d = *(const int4*)(e32 + Ee + e0);
        src[0] = s.x; src[1] = s.y; src[2] = s.z; src[3] = s.w;
        dst[0] = d.x; dst[1] = d.y; dst[2] = d.z; dst[3] = d.w;
    }

    // ---- Addresses + gathers (all 8 in flight)
    uint32_t key[4];
    uint4 av[4], bv[4];
#pragma unroll
    for (int r = 0; r < 4; r++) {
        const uint32_t srow = base + ((uint32_t)src[r] << 9);
        const uint32_t drow = base + ((uint32_t)dst[r] << 9);
        key[r] = srow + (uint32_t)dst[r];
        av[r] = *(const uint4*)(AB + srow + ch);
        bv[r] = *(const uint4*)(AB + drow + 256 + ch);
    }

    float acc[4];
#pragma unroll
    for (int r = 0; r < 4; r++) {
        const __nv_bfloat162* ap = (const __nv_bfloat162*)&av[r];
        const __nv_bfloat162* bp = (const __nv_bfloat162*)&bv[r];
        const __nv_bfloat162 z2 = __float2bfloat162_rn(0.f);
        float a = 0.f;
#pragma unroll
        for (int p = 0; p < 4; p++) {
            __nv_bfloat162 h = __hmax2(__hadd2(ap[p], bp[p]), z2);
            float2 f = bf2_to_f2(*(const uint32_t*)&h);
            a = fmaf(f.x, w[2 * p], a);
            a = fmaf(f.y, w[2 * p + 1], a);
        }
        acc[r] = a;
    }

    // ---- Multi-edge reduction: 6 shfls reduce all 4 edges.
    const bool hi16 = (lane & 16) != 0;
    float send, recv, sA, sB, t;

    send = hi16 ? acc[0] : acc[2];
    recv = __shfl_xor_sync(0xffffffffu, send, 16);
    sA   = (hi16 ? acc[2] : acc[0]) + recv;   // lanes<16: e0, lanes>=16: e2

    send = hi16 ? acc[1] : acc[3];
    recv = __shfl_xor_sync(0xffffffffu, send, 16);
    sB   = (hi16 ? acc[3] : acc[1]) + recv;   // lanes<16: e1, lanes>=16: e3

    const bool hi8 = (lane & 8) != 0;
    send = hi8 ? sA : sB;
    recv = __shfl_xor_sync(0xffffffffu, send, 8);
    t    = (hi8 ? sB : sA) + recv;            // group g holds edge g

    t += __shfl_xor_sync(0xffffffffu, t, 4);
    t += __shfl_xor_sync(0xffffffffu, t, 2);
    t += __shfl_xor_sync(0xffffffffu, t, 1);

    const int g = lane >> 3;
    const uint32_t k = (g & 2) ? ((g & 1) ? key[3] : key[2])
                               : ((g & 1) ? key[1] : key[0]);
    const float s = 1.0f / (1.0f + __expf(-(t + b2v)));
    if ((lane & 7) == 0)
        out[k] = s;
}

// ---------------------------------------------------------------------------
extern "C" void kernel_launch(void* const* d_in, const int* in_sizes, int n_in,
                              void* d_out, int out_size)
{
    const float* features = (const float*)d_in[0];   // (8,512,256)
    const float* W1       = (const float*)d_in[1];   // (512,256)
    const float* b1       = (const float*)d_in[2];   // (256)
    const float* W2       = (const float*)d_in[3];   // (256,1)
    const float* b2       = (const float*)d_in[4];   // (1)
    const void*  edge     = d_in[5];                 // (2,16384) int32 or int64
    float*       out      = (float*)d_out;           // (8,512,512)

    __nv_bfloat16* AB;
    cudaGetSymbolAddress((void**)&AB, g_AB);

    cudaFuncSetAttribute(gemm_fused_kernel,
                         cudaFuncAttributeMaxDynamicSharedMemorySize, SMEM_TOTAL);

    // Phase 1 (fused): zero out + B convert + cp.async f32 A stream + GEMM
    dim3 ggrid(8, 32);   // N-tiles x M-tiles
    gemm_fused_kernel<<<ggrid, 256, SMEM_TOTAL>>>(features, W1, b1, AB, out);

    // Phase 2: edge MLP tail + scatter (4 edges per warp)
    edge_kernel<<<4096, 256>>>(AB, W2, b2, edge, out);
}